// round 9
// baseline (speedup 1.0000x reference)
#include <cuda_runtime.h>
#include <math.h>
#include <stdint.h>

#define BATCH 4
#define SEQ   2048
#define EMD   768
#define HEADS 8
#define HDIM  96
#define MROWS (BATCH*SEQ)

#define TQ 32
#define TK 16
#define KSPLIT 4
#define KCHUNK (SEQ/KSPLIT)
#define KSTR 772
#define ESTR 17
#define SQRT_EMD 27.712812921102035f

typedef unsigned long long ull;

__device__ __forceinline__ ull pk2(float lo, float hi) {
    ull r; asm("mov.b64 %0,{%1,%2};" : "=l"(r) : "f"(lo), "f"(hi)); return r;
}
__device__ __forceinline__ void upk2(ull v, float& lo, float& hi) {
    asm("mov.b64 {%0,%1},%2;" : "=f"(lo), "=f"(hi) : "l"(v));
}
#define FFMA2(d,a,b,c) asm("fma.rn.f32x2 %0,%1,%2,%3;" : "=l"(d) : "l"(a), "l"(b), "l"(c))

__device__ __forceinline__ uint32_t f2tf32(float x) {
    uint32_t r; asm("cvt.rna.tf32.f32 %0, %1;" : "=r"(r) : "f"(x)); return r;
}
// C(16x8,f32) += A(16x8,tf32,row) * B(8x8,tf32,col)
__device__ __forceinline__ void mma_tf32(float* d, const uint32_t* a, const uint32_t* b) {
    asm volatile(
        "mma.sync.aligned.m16n8k8.row.col.f32.tf32.tf32.f32 "
        "{%0,%1,%2,%3}, {%4,%5,%6,%7}, {%8,%9}, {%0,%1,%2,%3};"
        : "+f"(d[0]), "+f"(d[1]), "+f"(d[2]), "+f"(d[3])
        : "r"(a[0]), "r"(a[1]), "r"(a[2]), "r"(a[3]), "r"(b[0]), "r"(b[1]));
}

// Scratch (allocation-free rule: __device__ globals)
__device__ float g_Q [MROWS*EMD];
__device__ float g_K [MROWS*EMD];
__device__ float g_V [MROWS*EMD];
__device__ float g_O0[MROWS*EMD];
__device__ float g_O1[MROWS*EMD];
__device__ float g_O2[MROWS*EMD];
__device__ float g_O3[MROWS*EMD];

// ---------------------------------------------------------------------------
// mma.sync tf32 NT GEMM: C[m,n] = sum_k Asum[m,k] * W[n,k] + bias[n]
// Asum = A0 (+A1+A2+A3 if A1 != null).  128x128 CTA tile, BK=32,
// 8 warps (2 M x 4 N), warp tile 64x32 via m16n8k8 tf32, fp32 accumulate.
// Smem stride 36 words -> conflict-free fragment LDS.
// blockIdx.z selects (W,bias,C) triple for the fused QKV launch.
// ---------------------------------------------------------------------------
__global__ __launch_bounds__(256)
void gemm_mma(const float* __restrict__ A0, const float* __restrict__ A1,
              const float* __restrict__ A2, const float* __restrict__ A3,
              const float* __restrict__ W0, const float* __restrict__ bv0, float* __restrict__ C0,
              const float* __restrict__ W1, const float* __restrict__ bv1, float* __restrict__ C1,
              const float* __restrict__ W2, const float* __restrict__ bv2, float* __restrict__ C2)
{
    const float* W    = W0;
    const float* bias = bv0;
    float*       C    = C0;
    if (blockIdx.z == 1) { W = W1; bias = bv1; C = C1; }
    if (blockIdx.z == 2) { W = W2; bias = bv2; C = C2; }

    __shared__ __align__(16) uint32_t As[128][36];   // tf32 bits, [m][k]
    __shared__ __align__(16) uint32_t Bs[128][36];   // tf32 bits, [n][k]

    const int tid  = threadIdx.x;
    const int w    = tid >> 5;
    const int lane = tid & 31;
    const int wm   = w & 1;          // 2 M-warps of 64 rows
    const int wn   = w >> 1;         // 4 N-warps of 32 cols
    const int gid  = lane >> 2;      // groupID 0..7
    const int tig  = lane & 3;       // thread-in-group 0..3
    const int m0   = blockIdx.x * 128;
    const int n0   = blockIdx.y * 128;

    const int lr = tid >> 1;         // fill row 0..127
    const int lc = (tid & 1) * 16;   // fill col 0 or 16

    const float* Ap = A0 + (size_t)(m0 + lr) * EMD + lc;
    const float* Wp = W  + (size_t)(n0 + lr) * EMD + lc;
    const bool sum4 = (A1 != (const float*)0);
    const size_t aoff = (size_t)(m0 + lr) * EMD + lc;

    float acc[4][4][4];
    #pragma unroll
    for (int i = 0; i < 4; i++)
        #pragma unroll
        for (int j = 0; j < 4; j++)
            #pragma unroll
            for (int r = 0; r < 4; r++) acc[i][j][r] = 0.f;

    for (int k0 = 0; k0 < EMD; k0 += 32) {
        // ---- fill: 16 A + 16 W tf32 values per thread, STS.128 ----
        #pragma unroll
        for (int ci = 0; ci < 4; ci++) {
            float4 v = *(const float4*)(Ap + k0 + ci*4);
            if (sum4) {
                const float4 a1 = *(const float4*)(A1 + aoff + k0 + ci*4);
                const float4 a2 = *(const float4*)(A2 + aoff + k0 + ci*4);
                const float4 a3 = *(const float4*)(A3 + aoff + k0 + ci*4);
                v.x = (v.x + a1.x) + (a2.x + a3.x);
                v.y = (v.y + a1.y) + (a2.y + a3.y);
                v.z = (v.z + a1.z) + (a2.z + a3.z);
                v.w = (v.w + a1.w) + (a2.w + a3.w);
            }
            uint4 t;
            t.x = f2tf32(v.x); t.y = f2tf32(v.y); t.z = f2tf32(v.z); t.w = f2tf32(v.w);
            *(uint4*)&As[lr][lc + ci*4] = t;
            const float4 wv = *(const float4*)(Wp + k0 + ci*4);
            uint4 u;
            u.x = f2tf32(wv.x); u.y = f2tf32(wv.y); u.z = f2tf32(wv.z); u.w = f2tf32(wv.w);
            *(uint4*)&Bs[lr][lc + ci*4] = u;
        }
        __syncthreads();

        // ---- compute: 4 k-steps of m16n8k8 ----
        #pragma unroll
        for (int ks = 0; ks < 4; ks++) {
            uint32_t a[4][4], b[4][2];
            #pragma unroll
            for (int i = 0; i < 4; i++) {
                const uint32_t* ap = &As[wm*64 + i*16 + gid][ks*8 + tig];
                a[i][0] = ap[0];
                a[i][1] = ap[8*36];
                a[i][2] = ap[4];
                a[i][3] = ap[8*36 + 4];
            }
            #pragma unroll
            for (int j = 0; j < 4; j++) {
                const uint32_t* bp = &Bs[wn*32 + j*8 + gid][ks*8 + tig];
                b[j][0] = bp[0];
                b[j][1] = bp[4];
            }
            #pragma unroll
            for (int i = 0; i < 4; i++)
                #pragma unroll
                for (int j = 0; j < 4; j++)
                    mma_tf32(acc[i][j], a[i], b[j]);
        }
        __syncthreads();
    }

    // ---- epilogue: bias + store (2 float2 per (i,j)) ----
    #pragma unroll
    for (int i = 0; i < 4; i++) {
        const int m = m0 + wm*64 + i*16 + gid;
        #pragma unroll
        for (int j = 0; j < 4; j++) {
            const int n = n0 + wn*32 + j*8 + tig*2;
            const float2 bv = *(const float2*)&bias[n];
            float2 o0, o1;
            o0.x = acc[i][j][0] + bv.x; o0.y = acc[i][j][1] + bv.y;
            o1.x = acc[i][j][2] + bv.x; o1.y = acc[i][j][3] + bv.y;
            *(float2*)(C + (size_t)m*EMD + n)     = o0;
            *(float2*)(C + (size_t)(m+8)*EMD + n) = o1;
        }
    }
}

// ---------------------------------------------------------------------------
// Fused attention, softmax over HEADS axis. FFMA2 core, split-K4 (exact:
// head-softmax has no coupling across k; partial O's summed in gemm_mma).
// CTA: (b, 32-row q-tile, k-quarter). 8 warps = 1 per head.  (unchanged R5)
// ---------------------------------------------------------------------------
__global__ __launch_bounds__(256)
void attn_kernel()
{
    extern __shared__ float sm[];
    float* Qs = sm;
    float* Ks = Qs + TQ*KSTR;
    float* Vs = Ks + TK*KSTR;
    float* Es = Vs + TK*KSTR;

    const int b    = blockIdx.y;
    const int q0   = blockIdx.x * TQ;
    const int kh   = blockIdx.z;
    const int tid  = threadIdx.x;
    const int warp = tid >> 5;
    const int lane = tid & 31;
    const int qg   = lane >> 3;
    const int kg   = lane & 7;
    const int hb   = warp * HDIM;

    for (int j = tid; j < TQ*(EMD/4); j += 256) {
        const int r = j / (EMD/4);
        const int c = (j % (EMD/4)) * 4;
        *(float4*)(Qs + r*KSTR + c) =
            *(const float4*)(g_Q + (size_t)(b*SEQ + q0 + r)*EMD + c);
    }

    ull Oacc[8][6];
    #pragma unroll
    for (int i = 0; i < 8; i++)
        #pragma unroll
        for (int j = 0; j < 6; j++) Oacc[i][j] = 0ull;

    const int kbeg = kh * KCHUNK;
    for (int k0 = kbeg; k0 < kbeg + KCHUNK; k0 += TK) {
        __syncthreads();

        for (int j = tid; j < TK*(EMD/4); j += 256) {
            const int r = j / (EMD/4);
            const int c = (j % (EMD/4)) * 4;
            const size_t g = (size_t)(b*SEQ + k0 + r)*EMD + c;
            *(float4*)(Ks + r*KSTR + c) = *(const float4*)(g_K + g);
            *(float4*)(Vs + r*KSTR + c) = *(const float4*)(g_V + g);
        }
        __syncthreads();

        ull e2[8][2];
        #pragma unroll
        for (int i = 0; i < 8; i++) { e2[i][0] = 0ull; e2[i][1] = 0ull; }

        const float* qbase  = Qs + (size_t)qg*KSTR + hb;
        const float* k0base = Ks + (size_t)kg*KSTR + hb;
        const float* k1base = Ks + (size_t)(kg+8)*KSTR + hb;

        #pragma unroll
        for (int d = 0; d < HDIM; d += 4) {
            const ulonglong2 kv0 = *(const ulonglong2*)(k0base + d);
            const ulonglong2 kv1 = *(const ulonglong2*)(k1base + d);
            #pragma unroll
            for (int i = 0; i < 8; i++) {
                const ulonglong2 qv = *(const ulonglong2*)(qbase + (size_t)(4*i)*KSTR + d);
                FFMA2(e2[i][0], qv.x, kv0.x, e2[i][0]);
                FFMA2(e2[i][0], qv.y, kv0.y, e2[i][0]);
                FFMA2(e2[i][1], qv.x, kv1.x, e2[i][1]);
                FFMA2(e2[i][1], qv.y, kv1.y, e2[i][1]);
            }
        }

        #pragma unroll
        for (int i = 0; i < 8; i++) {
            float lo, hi;
            upk2(e2[i][0], lo, hi); const float s0 = lo + hi;
            upk2(e2[i][1], lo, hi); const float s1 = lo + hi;
            const int row = warp*TQ + qg + 4*i;
            Es[row*ESTR + kg    ] = __expf(s0);
            Es[row*ESTR + kg + 8] = __expf(s1);
        }
        __syncthreads();

        #pragma unroll
        for (int pp = 0; pp < 2; pp++) {
            const int p = tid*2 + pp;
            const int q = p >> 4;
            const int k = p & 15;
            float s = 0.f;
            #pragma unroll
            for (int h = 0; h < HEADS; h++) s += Es[(h*TQ + q)*ESTR + k];
            const float inv = 1.0f / (s * SQRT_EMD);
            #pragma unroll
            for (int h = 0; h < HEADS; h++) Es[(h*TQ + q)*ESTR + k] *= inv;
        }
        __syncthreads();

        #pragma unroll
        for (int k = 0; k < TK; k++) {
            ull a2[8];
            #pragma unroll
            for (int i = 0; i < 8; i++) {
                const float av = Es[(warp*TQ + qg + 4*i)*ESTR + k];
                a2[i] = pk2(av, av);
            }
            const float* vp = Vs + (size_t)k*KSTR + hb + kg*12;
            const ulonglong2 v0 = *(const ulonglong2*)(vp + 0);
            const ulonglong2 v1 = *(const ulonglong2*)(vp + 4);
            const ulonglong2 v2 = *(const ulonglong2*)(vp + 8);
            #pragma unroll
            for (int i = 0; i < 8; i++) {
                FFMA2(Oacc[i][0], a2[i], v0.x, Oacc[i][0]);
                FFMA2(Oacc[i][1], a2[i], v0.y, Oacc[i][1]);
                FFMA2(Oacc[i][2], a2[i], v1.x, Oacc[i][2]);
                FFMA2(Oacc[i][3], a2[i], v1.y, Oacc[i][3]);
                FFMA2(Oacc[i][4], a2[i], v2.x, Oacc[i][4]);
                FFMA2(Oacc[i][5], a2[i], v2.y, Oacc[i][5]);
            }
        }
    }

    float* Obase = (kh == 0) ? g_O0 : (kh == 1) ? g_O1 : (kh == 2) ? g_O2 : g_O3;
    #pragma unroll
    for (int i = 0; i < 8; i++) {
        float* op = Obase + (size_t)(b*SEQ + q0 + qg + 4*i)*EMD + hb + kg*12;
        float f[12];
        upk2(Oacc[i][0], f[0], f[1]);  upk2(Oacc[i][1], f[2],  f[3]);
        upk2(Oacc[i][2], f[4], f[5]);  upk2(Oacc[i][3], f[6],  f[7]);
        upk2(Oacc[i][4], f[8], f[9]);  upk2(Oacc[i][5], f[10], f[11]);
        float4 o0, o1, o2;
        o0.x=f[0]; o0.y=f[1]; o0.z=f[2];  o0.w=f[3];
        o1.x=f[4]; o1.y=f[5]; o1.z=f[6];  o1.w=f[7];
        o2.x=f[8]; o2.y=f[9]; o2.z=f[10]; o2.w=f[11];
        *(float4*)(op + 0) = o0;
        *(float4*)(op + 4) = o1;
        *(float4*)(op + 8) = o2;
    }
}

// ---------------------------------------------------------------------------
extern "C" void kernel_launch(void* const* d_in, const int* in_sizes, int n_in,
                              void* d_out, int out_size)
{
    const float* x  = (const float*)d_in[0];
    const float* Wq = (const float*)d_in[1];
    const float* bq = (const float*)d_in[2];
    const float* Wk = (const float*)d_in[3];
    const float* bk = (const float*)d_in[4];
    const float* Wv = (const float*)d_in[5];
    const float* bv = (const float*)d_in[6];
    const float* Wo = (const float*)d_in[7];
    const float* bo = (const float*)d_in[8];
    float* out = (float*)d_out;

    float *Qp, *Kp, *Vp, *O0p, *O1p, *O2p, *O3p;
    cudaGetSymbolAddress((void**)&Qp,  g_Q);
    cudaGetSymbolAddress((void**)&Kp,  g_K);
    cudaGetSymbolAddress((void**)&Vp,  g_V);
    cudaGetSymbolAddress((void**)&O0p, g_O0);
    cudaGetSymbolAddress((void**)&O1p, g_O1);
    cudaGetSymbolAddress((void**)&O2p, g_O2);
    cudaGetSymbolAddress((void**)&O3p, g_O3);

    const int smem_bytes = ((TQ + 2*TK)*KSTR + HEADS*TQ*ESTR) * (int)sizeof(float); // 215040
    cudaFuncSetAttribute(attn_kernel, cudaFuncAttributeMaxDynamicSharedMemorySize, smem_bytes);

    // 1) Fused QKV projections on tensor cores (tf32 mma.sync; z selects Q/K/V)
    gemm_mma<<<dim3(MROWS/128, EMD/128, 3), 256>>>(
        x, (const float*)0, (const float*)0, (const float*)0,
        Wq, bq, Qp, Wk, bk, Kp, Wv, bv, Vp);

    // 2) Fused head-axis-softmax attention, split-K4 (FFMA2)
    attn_kernel<<<dim3(SEQ/TQ, BATCH, KSPLIT), 256, smem_bytes>>>();

    // 3) Output projection on tensor cores (A = sum of 4 partial O buffers)
    gemm_mma<<<dim3(MROWS/128, EMD/128, 1), 256>>>(
        O0p, O1p, O2p, O3p,
        Wo, bo, out, Wo, bo, out, Wo, bo, out);
}

// round 11
// speedup vs baseline: 1.7107x; 1.7107x over previous
#include <cuda_runtime.h>
#include <math.h>
#include <stdint.h>

#define BATCH 4
#define SEQ   2048
#define EMD   768
#define HEADS 8
#define HDIM  96
#define MROWS (BATCH*SEQ)

#define TQ 32
#define TK 16
#define KSPLIT 4
#define KCHUNK (SEQ/KSPLIT)
#define QSTR 776           // bf16 elements per row (1552 B, 16B-aligned)
#define VSTR 772           // fp32 elements per row
#define ESTR 17
#define SQRT_EMD 27.712812921102035f

typedef unsigned long long ull;

__device__ __forceinline__ ull pk2(float lo, float hi) {
    ull r; asm("mov.b64 %0,{%1,%2};" : "=l"(r) : "f"(lo), "f"(hi)); return r;
}
__device__ __forceinline__ void upk2(ull v, float& lo, float& hi) {
    asm("mov.b64 {%0,%1},%2;" : "=f"(lo), "=f"(hi) : "l"(v));
}
#define FFMA2(d,a,b,c) asm("fma.rn.f32x2 %0,%1,%2,%3;" : "=l"(d) : "l"(a), "l"(b), "l"(c))

__device__ __forceinline__ uint32_t f2tf32(float x) {
    uint32_t r; asm("cvt.rna.tf32.f32 %0, %1;" : "=r"(r) : "f"(x)); return r;
}
// C(16x8,f32) += A(16x8,tf32,row) * B(8x8,tf32,col)
__device__ __forceinline__ void mma_tf32(float* d, const uint32_t* a, const uint32_t* b) {
    asm volatile(
        "mma.sync.aligned.m16n8k8.row.col.f32.tf32.tf32.f32 "
        "{%0,%1,%2,%3}, {%4,%5,%6,%7}, {%8,%9}, {%0,%1,%2,%3};"
        : "+f"(d[0]), "+f"(d[1]), "+f"(d[2]), "+f"(d[3])
        : "r"(a[0]), "r"(a[1]), "r"(a[2]), "r"(a[3]), "r"(b[0]), "r"(b[1]));
}
// C(16x8,f32) += A(16x16,bf16,row) * B(16x8,bf16,col)
__device__ __forceinline__ void mma_bf16(float* d, const uint32_t* a, const uint32_t* b) {
    asm volatile(
        "mma.sync.aligned.m16n8k16.row.col.f32.bf16.bf16.f32 "
        "{%0,%1,%2,%3}, {%4,%5,%6,%7}, {%8,%9}, {%0,%1,%2,%3};"
        : "+f"(d[0]), "+f"(d[1]), "+f"(d[2]), "+f"(d[3])
        : "r"(a[0]), "r"(a[1]), "r"(a[2]), "r"(a[3]), "r"(b[0]), "r"(b[1]));
}
// pack 2 floats to bf16x2 (lo -> low half)
__device__ __forceinline__ uint32_t bfx2(float lo, float hi) {
    uint32_t r; asm("cvt.rn.bf16x2.f32 %0, %1, %2;" : "=r"(r) : "f"(hi), "f"(lo)); return r;
}
// split (x,y) into hi-pair (bf16 rn) and lo-pair (residual as bf16)
__device__ __forceinline__ void split2(float x, float y, uint32_t& hp, uint32_t& lp) {
    const uint32_t bx = __float_as_uint(x), by = __float_as_uint(y);
    const uint32_t rx = (bx + 0x7FFFu + ((bx >> 16) & 1u)) & 0xFFFF0000u;
    const uint32_t ry = (by + 0x7FFFu + ((by >> 16) & 1u)) & 0xFFFF0000u;
    hp = ry | (rx >> 16);
    lp = bfx2(x - __uint_as_float(rx), y - __uint_as_float(ry));
}

// Scratch (allocation-free rule: __device__ globals)
__device__ float g_Q [MROWS*EMD];
__device__ float g_K [MROWS*EMD];
__device__ float g_V [MROWS*EMD];
__device__ float g_O0[MROWS*EMD];
__device__ float g_O1[MROWS*EMD];
__device__ float g_O2[MROWS*EMD];
__device__ float g_O3[MROWS*EMD];

// ---------------------------------------------------------------------------
// mma.sync tf32 NT GEMM (single A): C[m,n] = sum_k A[m,k]*W[n,k] + bias[n]
// 128x128 tile, BK=32, 8 warps (2M x 4N), warp tile 64x32, fp32 accumulate.
// 2 CTAs/SM (regs capped at 128).  blockIdx.z selects (W,bias,C).
// ---------------------------------------------------------------------------
__global__ __launch_bounds__(256, 2)
void gemm_mma(const float* __restrict__ A,
              const float* __restrict__ W0, const float* __restrict__ bv0, float* __restrict__ C0,
              const float* __restrict__ W1, const float* __restrict__ bv1, float* __restrict__ C1,
              const float* __restrict__ W2, const float* __restrict__ bv2, float* __restrict__ C2)
{
    const float* W    = W0;
    const float* bias = bv0;
    float*       C    = C0;
    if (blockIdx.z == 1) { W = W1; bias = bv1; C = C1; }
    if (blockIdx.z == 2) { W = W2; bias = bv2; C = C2; }

    __shared__ __align__(16) uint32_t As[128][36];
    __shared__ __align__(16) uint32_t Bs[128][36];

    const int tid  = threadIdx.x;
    const int w    = tid >> 5;
    const int lane = tid & 31;
    const int wm   = w & 1;
    const int wn   = w >> 1;
    const int gid  = lane >> 2;
    const int tig  = lane & 3;
    const int m0   = blockIdx.x * 128;
    const int n0   = blockIdx.y * 128;

    const int lr = tid >> 1;
    const int lc = (tid & 1) * 16;

    const float* Ap = A + (size_t)(m0 + lr) * EMD + lc;
    const float* Wp = W + (size_t)(n0 + lr) * EMD + lc;

    float acc[4][4][4];
    #pragma unroll
    for (int i = 0; i < 4; i++)
        #pragma unroll
        for (int j = 0; j < 4; j++)
            #pragma unroll
            for (int r = 0; r < 4; r++) acc[i][j][r] = 0.f;

    for (int k0 = 0; k0 < EMD; k0 += 32) {
        #pragma unroll
        for (int ci = 0; ci < 4; ci++) {
            const float4 v  = *(const float4*)(Ap + k0 + ci*4);
            uint4 t;
            t.x = f2tf32(v.x); t.y = f2tf32(v.y); t.z = f2tf32(v.z); t.w = f2tf32(v.w);
            *(uint4*)&As[lr][lc + ci*4] = t;
            const float4 wv = *(const float4*)(Wp + k0 + ci*4);
            uint4 u;
            u.x = f2tf32(wv.x); u.y = f2tf32(wv.y); u.z = f2tf32(wv.z); u.w = f2tf32(wv.w);
            *(uint4*)&Bs[lr][lc + ci*4] = u;
        }
        __syncthreads();

        #pragma unroll
        for (int ks = 0; ks < 4; ks++) {
            uint32_t a[4][4], b[4][2];
            #pragma unroll
            for (int i = 0; i < 4; i++) {
                const uint32_t* ap = &As[wm*64 + i*16 + gid][ks*8 + tig];
                a[i][0] = ap[0];
                a[i][1] = ap[8*36];
                a[i][2] = ap[4];
                a[i][3] = ap[8*36 + 4];
            }
            #pragma unroll
            for (int j = 0; j < 4; j++) {
                const uint32_t* bp = &Bs[wn*32 + j*8 + gid][ks*8 + tig];
                b[j][0] = bp[0];
                b[j][1] = bp[4];
            }
            #pragma unroll
            for (int i = 0; i < 4; i++)
                #pragma unroll
                for (int j = 0; j < 4; j++)
                    mma_tf32(acc[i][j], a[i], b[j]);
        }
        __syncthreads();
    }

    #pragma unroll
    for (int i = 0; i < 4; i++) {
        const int m = m0 + wm*64 + i*16 + gid;
        #pragma unroll
        for (int j = 0; j < 4; j++) {
            const int n = n0 + wn*32 + j*8 + tig*2;
            const float2 bv = *(const float2*)&bias[n];
            float2 o0, o1;
            o0.x = acc[i][j][0] + bv.x; o0.y = acc[i][j][1] + bv.y;
            o1.x = acc[i][j][2] + bv.x; o1.y = acc[i][j][3] + bv.y;
            *(float2*)(C + (size_t)m*EMD + n)     = o0;
            *(float2*)(C + (size_t)(m+8)*EMD + n) = o1;
        }
    }
}

// ---------------------------------------------------------------------------
// Sum the 4 split-K partial O buffers into g_O0 (float4 grid-stride).
// ---------------------------------------------------------------------------
__global__ __launch_bounds__(256)
void presum_o()
{
    const size_t N = (size_t)MROWS * EMD / 4;
    float4*       o0 = (float4*)g_O0;
    const float4* o1 = (const float4*)g_O1;
    const float4* o2 = (const float4*)g_O2;
    const float4* o3 = (const float4*)g_O3;
    for (size_t i = (size_t)blockIdx.x * blockDim.x + threadIdx.x; i < N;
         i += (size_t)gridDim.x * blockDim.x) {
        float4 a = o0[i];
        const float4 b = o1[i], c = o2[i], d = o3[i];
        a.x = (a.x + b.x) + (c.x + d.x);
        a.y = (a.y + b.y) + (c.y + d.y);
        a.z = (a.z + b.z) + (c.z + d.z);
        a.w = (a.w + b.w) + (c.w + d.w);
        o0[i] = a;
    }
}

// ---------------------------------------------------------------------------
// Fused attention, softmax over HEADS axis. Split-K4.
// E = Q K^T via split-bf16 m16n8k16 MMA (hi/lo planes; error ~2^-18, fp32-class).
// exp -> Es (fp32), cross-head normalize (unchanged), AV via FFMA2 (unchanged).
// CTA: (b, 32-row q-tile, k-quarter). 8 warps = 1 per head.
// Smem: Qhi/Qlo bf16[32][776], Khi/Klo bf16[16][776], V f32[16][772],
//       Es f32[8*32][17]  -> 215808 B.
// ---------------------------------------------------------------------------
__global__ __launch_bounds__(256)
void attn_kernel()
{
    extern __shared__ char smx[];
    char*  Qhi = smx;                       // 49664
    char*  Qlo = smx + 49664;               // 49664
    char*  Khi = smx + 99328;               // 24832
    char*  Klo = smx + 124160;              // 24832
    float* Vs  = (float*)(smx + 148992);    // 49408
    float* Es  = (float*)(smx + 198400);    // 17408

    const int b    = blockIdx.y;
    const int q0   = blockIdx.x * TQ;
    const int kh   = blockIdx.z;
    const int tid  = threadIdx.x;
    const int warp = tid >> 5;              // head
    const int lane = tid & 31;
    const int gid  = lane >> 2;             // 0..7 (mma group)
    const int tig  = lane & 3;              // 0..3
    const int qg   = lane >> 3;             // 0..3 (AV mapping)
    const int kg   = lane & 7;              // 0..7
    const int hb   = warp * HDIM;           // col base (elements)

    // ---- Q tile -> bf16 hi/lo planes (once per CTA) ----
    for (int j = tid; j < TQ*(EMD/4); j += 256) {
        const int r  = j / (EMD/4);
        const int c4 = j % (EMD/4);
        const float4 v = *(const float4*)(g_Q + (size_t)(b*SEQ + q0 + r)*EMD + c4*4);
        uint32_t h0, l0, h1, l1;
        split2(v.x, v.y, h0, l0);
        split2(v.z, v.w, h1, l1);
        uint2 hh; hh.x = h0; hh.y = h1;
        uint2 ll; ll.x = l0; ll.y = l1;
        *(uint2*)(Qhi + ((size_t)r*QSTR + c4*4)*2) = hh;
        *(uint2*)(Qlo + ((size_t)r*QSTR + c4*4)*2) = ll;
    }

    ull Oacc[8][6];
    #pragma unroll
    for (int i = 0; i < 8; i++)
        #pragma unroll
        for (int j = 0; j < 6; j++) Oacc[i][j] = 0ull;

    const int kbeg = kh * KCHUNK;
    for (int k0 = kbeg; k0 < kbeg + KCHUNK; k0 += TK) {
        __syncthreads();   // prev AV reads of K/V/Es done; Q planes visible (iter 0)

        // ---- K tile -> bf16 hi/lo planes; V tile -> fp32 ----
        for (int j = tid; j < TK*(EMD/4); j += 256) {
            const int r  = j / (EMD/4);
            const int c4 = j % (EMD/4);
            const size_t g = (size_t)(b*SEQ + k0 + r)*EMD + c4*4;
            const float4 kv = *(const float4*)(g_K + g);
            uint32_t h0, l0, h1, l1;
            split2(kv.x, kv.y, h0, l0);
            split2(kv.z, kv.w, h1, l1);
            uint2 hh; hh.x = h0; hh.y = h1;
            uint2 ll; ll.x = l0; ll.y = l1;
            *(uint2*)(Khi + ((size_t)r*QSTR + c4*4)*2) = hh;
            *(uint2*)(Klo + ((size_t)r*QSTR + c4*4)*2) = ll;
            *(float4*)(Vs + (size_t)r*VSTR + c4*4) = *(const float4*)(g_V + g);
        }
        __syncthreads();

        // ---- E = Q K^T : 32x16 per warp, split-bf16, 72 MMAs ----
        float eacc[2][2][4];
        #pragma unroll
        for (int i = 0; i < 2; i++)
            #pragma unroll
            for (int j = 0; j < 2; j++)
                #pragma unroll
                for (int r = 0; r < 4; r++) eacc[i][j][r] = 0.f;

        #pragma unroll
        for (int s = 0; s < 6; s++) {
            const int cA = hb + s*16 + tig*2;   // element col within row
            uint32_t ah[2][4], al[2][4], bh[2][2], bl[2][2];
            #pragma unroll
            for (int i = 0; i < 2; i++) {
                const size_t ro = (size_t)(i*16 + gid)*QSTR + cA;
                const char* ph = Qhi + ro*2;
                ah[i][0] = *(const uint32_t*)(ph);
                ah[i][1] = *(const uint32_t*)(ph + (size_t)8*QSTR*2);
                ah[i][2] = *(const uint32_t*)(ph + 16);
                ah[i][3] = *(const uint32_t*)(ph + (size_t)8*QSTR*2 + 16);
                const char* pl = Qlo + ro*2;
                al[i][0] = *(const uint32_t*)(pl);
                al[i][1] = *(const uint32_t*)(pl + (size_t)8*QSTR*2);
                al[i][2] = *(const uint32_t*)(pl + 16);
                al[i][3] = *(const uint32_t*)(pl + (size_t)8*QSTR*2 + 16);
            }
            #pragma unroll
            for (int j = 0; j < 2; j++) {
                const size_t ro = (size_t)(j*8 + gid)*QSTR + cA;
                const char* ph = Khi + ro*2;
                bh[j][0] = *(const uint32_t*)(ph);
                bh[j][1] = *(const uint32_t*)(ph + 16);
                const char* pl = Klo + ro*2;
                bl[j][0] = *(const uint32_t*)(pl);
                bl[j][1] = *(const uint32_t*)(pl + 16);
            }
            #pragma unroll
            for (int i = 0; i < 2; i++)
                #pragma unroll
                for (int j = 0; j < 2; j++) {
                    mma_bf16(eacc[i][j], ah[i], bh[j]);
                    mma_bf16(eacc[i][j], ah[i], bl[j]);
                    mma_bf16(eacc[i][j], al[i], bh[j]);
                }
        }

        // exp -> Es (fp32)
        #pragma unroll
        for (int i = 0; i < 2; i++) {
            const int r0 = warp*TQ + i*16 + gid;
            #pragma unroll
            for (int j = 0; j < 2; j++) {
                const int c0 = j*8 + tig*2;
                Es[(r0    )*ESTR + c0    ] = __expf(eacc[i][j][0]);
                Es[(r0    )*ESTR + c0 + 1] = __expf(eacc[i][j][1]);
                Es[(r0 + 8)*ESTR + c0    ] = __expf(eacc[i][j][2]);
                Es[(r0 + 8)*ESTR + c0 + 1] = __expf(eacc[i][j][3]);
            }
        }
        __syncthreads();

        // Cross-head denominator + in-place normalize: 2 (q,k) pairs / thread
        #pragma unroll
        for (int pp = 0; pp < 2; pp++) {
            const int p = tid*2 + pp;
            const int q = p >> 4;
            const int k = p & 15;
            float s = 0.f;
            #pragma unroll
            for (int h = 0; h < HEADS; h++) s += Es[(h*TQ + q)*ESTR + k];
            const float inv = 1.0f / (s * SQRT_EMD);
            #pragma unroll
            for (int h = 0; h < HEADS; h++) Es[(h*TQ + q)*ESTR + k] *= inv;
        }
        __syncthreads();

        // ---- O += A @ V (FFMA2): rows qg+4i, d-cols kg*12..+11 ----
        #pragma unroll
        for (int k = 0; k < TK; k++) {
            ull a2[8];
            #pragma unroll
            for (int i = 0; i < 8; i++) {
                const float av = Es[(warp*TQ + qg + 4*i)*ESTR + k];
                a2[i] = pk2(av, av);
            }
            const float* vp = Vs + (size_t)k*VSTR + hb + kg*12;
            const ulonglong2 v0 = *(const ulonglong2*)(vp + 0);
            const ulonglong2 v1 = *(const ulonglong2*)(vp + 4);
            const ulonglong2 v2 = *(const ulonglong2*)(vp + 8);
            #pragma unroll
            for (int i = 0; i < 8; i++) {
                FFMA2(Oacc[i][0], a2[i], v0.x, Oacc[i][0]);
                FFMA2(Oacc[i][1], a2[i], v0.y, Oacc[i][1]);
                FFMA2(Oacc[i][2], a2[i], v1.x, Oacc[i][2]);
                FFMA2(Oacc[i][3], a2[i], v1.y, Oacc[i][3]);
                FFMA2(Oacc[i][4], a2[i], v2.x, Oacc[i][4]);
                FFMA2(Oacc[i][5], a2[i], v2.y, Oacc[i][5]);
            }
        }
    }

    // Write partial O in [M, 768] layout (col = h*96 + d)
    float* Obase = (kh == 0) ? g_O0 : (kh == 1) ? g_O1 : (kh == 2) ? g_O2 : g_O3;
    #pragma unroll
    for (int i = 0; i < 8; i++) {
        float* op = Obase + (size_t)(b*SEQ + q0 + qg + 4*i)*EMD + hb + kg*12;
        float f[12];
        upk2(Oacc[i][0], f[0], f[1]);  upk2(Oacc[i][1], f[2],  f[3]);
        upk2(Oacc[i][2], f[4], f[5]);  upk2(Oacc[i][3], f[6],  f[7]);
        upk2(Oacc[i][4], f[8], f[9]);  upk2(Oacc[i][5], f[10], f[11]);
        float4 o0, o1, o2;
        o0.x=f[0]; o0.y=f[1]; o0.z=f[2];  o0.w=f[3];
        o1.x=f[4]; o1.y=f[5]; o1.z=f[6];  o1.w=f[7];
        o2.x=f[8]; o2.y=f[9]; o2.z=f[10]; o2.w=f[11];
        *(float4*)(op + 0) = o0;
        *(float4*)(op + 4) = o1;
        *(float4*)(op + 8) = o2;
    }
}

// ---------------------------------------------------------------------------
extern "C" void kernel_launch(void* const* d_in, const int* in_sizes, int n_in,
                              void* d_out, int out_size)
{
    const float* x  = (const float*)d_in[0];
    const float* Wq = (const float*)d_in[1];
    const float* bq = (const float*)d_in[2];
    const float* Wk = (const float*)d_in[3];
    const float* bk = (const float*)d_in[4];
    const float* Wv = (const float*)d_in[5];
    const float* bv = (const float*)d_in[6];
    const float* Wo = (const float*)d_in[7];
    const float* bo = (const float*)d_in[8];
    float* out = (float*)d_out;

    float *Qp, *Kp, *Vp, *O0p;
    cudaGetSymbolAddress((void**)&Qp,  g_Q);
    cudaGetSymbolAddress((void**)&Kp,  g_K);
    cudaGetSymbolAddress((void**)&Vp,  g_V);
    cudaGetSymbolAddress((void**)&O0p, g_O0);

    const int smem_bytes = 215808;
    cudaFuncSetAttribute(attn_kernel, cudaFuncAttributeMaxDynamicSharedMemorySize, smem_bytes);

    // 1) Fused QKV projections (tf32 mma.sync; z selects Q/K/V)
    gemm_mma<<<dim3(MROWS/128, EMD/128, 3), 256>>>(
        x, Wq, bq, Qp, Wk, bk, Kp, Wv, bv, Vp);

    // 2) Fused head-axis-softmax attention, split-K4 (bf16-split E MMA + FFMA2 AV)
    attn_kernel<<<dim3(SEQ/TQ, BATCH, KSPLIT), 256, smem_bytes>>>();

    // 3) Sum split-K partials into g_O0
    presum_o<<<2048, 256>>>();

    // 4) Output projection (tf32 mma.sync) -> d_out
    gemm_mma<<<dim3(MROWS/128, EMD/128, 1), 256>>>(
        O0p, Wo, bo, out, Wo, bo, out, Wo, bo, out);
}